// round 1
// baseline (speedup 1.0000x reference)
#include <cuda_runtime.h>
#include <cuda_bf16.h>

#define M_PTS   200000
#define N_CAM   6
#define C_IMG   96
#define H_FEAT  32
#define W_FEAT  88
#define PTS_DIM 128
#define KIN     224           // 128 + 96
#define GZ      32
#define GY      512
#define GX      448
#define GRID_N  (GZ*GY*GX)    // 7,340,032

#define NB_SELF   1332
#define NB_OTHER  57
#define NBLK      (NB_SELF + 26*NB_OTHER)

#define CONV_W_SMEM (KIN*PTS_DIM*4)          // 114688 bytes
#define CONV_SMEM   (CONV_W_SMEM + 512*8 + 16)

// ---------------- device globals (scratch; no cudaMalloc allowed) ----------------
__device__ float g_imgT[N_CAM*H_FEAT*W_FEAT*C_IMG];   // NHWC transposed image feats
__device__ int   g_grid[GRID_N];
__device__ float g_sampled[(size_t)M_PTS*C_IMG];
__device__ float g_acc[(size_t)M_PTS*PTS_DIM];
__device__ float g_cam[N_CAM*24];                     // per cam: P|q rows (12), A|b rows (8)
__device__ float g_bnscale[PTS_DIM];
__device__ float g_bnbias[PTS_DIM];

// ---------------- setup: matrix precompute + BN constants ----------------
__global__ void setup_kernel(const float* __restrict__ l2i,
                             const float* __restrict__ iaug,
                             const float* __restrict__ laug,
                             const float* __restrict__ gamma,
                             const float* __restrict__ beta,
                             const float* __restrict__ mean,
                             const float* __restrict__ var) {
    int t = threadIdx.x;
    if (t < PTS_DIM) {
        float s = rsqrtf(var[t] + 1e-5f) * gamma[t];
        g_bnscale[t] = s;
        g_bnbias[t]  = beta[t] - mean[t] * s;
    }
    if (t == 0) {
        // inverse of lidar_aug 3x3
        float a0=laug[0],a1=laug[1],a2=laug[2];
        float a3=laug[4],a4=laug[5],a5=laug[6];
        float a6=laug[8],a7=laug[9],a8=laug[10];
        float tx=laug[3], ty=laug[7], tz=laug[11];
        float det = a0*(a4*a8-a5*a7) - a1*(a3*a8-a5*a6) + a2*(a3*a7-a4*a6);
        float id = 1.0f/det;
        float inv[9] = {
            (a4*a8-a5*a7)*id, (a2*a7-a1*a8)*id, (a1*a5-a2*a4)*id,
            (a5*a6-a3*a8)*id, (a0*a8-a2*a6)*id, (a2*a3-a0*a5)*id,
            (a3*a7-a4*a6)*id, (a1*a6-a0*a7)*id, (a0*a4-a1*a3)*id };
        for (int n = 0; n < N_CAM; n++) {
            const float* L = l2i + n*16;
            float P[9], q[3];
            for (int r = 0; r < 3; r++) {
                for (int c = 0; c < 3; c++) {
                    P[r*3+c] = L[r*4+0]*inv[0*3+c] + L[r*4+1]*inv[1*3+c] + L[r*4+2]*inv[2*3+c];
                }
                q[r] = L[r*4+3] - (P[r*3+0]*tx + P[r*3+1]*ty + P[r*3+2]*tz);
            }
            float* gc = g_cam + n*24;
            for (int r = 0; r < 3; r++) {
                gc[r*4+0]=P[r*3+0]; gc[r*4+1]=P[r*3+1]; gc[r*4+2]=P[r*3+2]; gc[r*4+3]=q[r];
            }
            const float* A = iaug + n*16;
            for (int r = 0; r < 2; r++) {
                gc[12+r*4+0]=A[r*4+0]; gc[12+r*4+1]=A[r*4+1]; gc[12+r*4+2]=A[r*4+2]; gc[12+r*4+3]=A[r*4+3];
            }
        }
    }
}

// ---------------- transpose img_feats NCHW -> NHWC ----------------
__global__ void transpose_kernel(const float* __restrict__ img) {
    int o = blockIdx.x * 256 + threadIdx.x;
    const int TOT = N_CAM*H_FEAT*W_FEAT*C_IMG;
    if (o >= TOT) return;
    int c = o % C_IMG; int rest = o / C_IMG;
    int x = rest % W_FEAT; rest /= W_FEAT;
    int y = rest % H_FEAT; int n = rest / H_FEAT;
    g_imgT[o] = img[(((size_t)n*C_IMG + c)*H_FEAT + y)*W_FEAT + x];
}

// ---------------- grid init / scatter ----------------
__global__ void init_grid_kernel() {
    int idx = blockIdx.x * 256 + threadIdx.x;
    if (idx < GRID_N/4) ((int4*)g_grid)[idx] = make_int4(-1,-1,-1,-1);
}

__global__ void scatter_kernel(const int* __restrict__ vc) {
    int i = blockIdx.x * 256 + threadIdx.x;
    if (i >= M_PTS) return;
    int4 c4 = ((const int4*)vc)[i];
    int cell = (c4.y*GY + c4.z)*GX + c4.w;
    atomicMax(&g_grid[cell], i);     // last-write-wins (highest index) for duplicates
}

__global__ void zero_acc_kernel() {
    int idx = blockIdx.x * 256 + threadIdx.x;
    if (idx < (M_PTS*PTS_DIM)/4) ((float4*)g_acc)[idx] = make_float4(0.f,0.f,0.f,0.f);
}

// ---------------- projection + bilinear sampling (warp per voxel) ----------------
__global__ void sample_kernel(const int* __restrict__ vc) {
    int warp = (blockIdx.x * blockDim.x + threadIdx.x) >> 5;
    int lane = threadIdx.x & 31;
    if (warp >= M_PTS) return;
    int4 c4 = ((const int4*)vc)[warp];
    float px = (float)c4.w, py = (float)c4.z, pz = (float)c4.y;  // (x,y,z)
    float4 acc = make_float4(0.f,0.f,0.f,0.f);

    #pragma unroll 1
    for (int n = 0; n < N_CAM; n++) {
        const float* cam = g_cam + n*24;
        float X = cam[0]*px + cam[1]*py + cam[2]*pz  + cam[3];
        float Y = cam[4]*px + cam[5]*py + cam[6]*pz  + cam[7];
        float Z = cam[8]*px + cam[9]*py + cam[10]*pz + cam[11];
        float z = fminf(fmaxf(Z, 1e-5f), 100000.0f);
        float rz = 1.0f / z;
        float vx = X*rz, vy = Y*rz;
        float u = cam[12]*vx + cam[13]*vy + cam[14]*z + cam[15];
        float v = cam[16]*vx + cam[17]*vy + cam[18]*z + cam[19];
        // x = (gx+1)*0.5*(W-1) simplifies to u * (W-1)/ORI_W
        float xf = u * (87.0f/704.0f);
        float yf = v * (31.0f/256.0f);
        float x0 = floorf(xf), y0 = floorf(yf);
        float wx1 = xf - x0, wy1 = yf - y0;
        float wx0 = 1.0f - wx1, wy0 = 1.0f - wy1;

        float cx[4] = {x0, x0+1.0f, x0,      x0+1.0f};
        float cy[4] = {y0, y0,      y0+1.0f, y0+1.0f};
        float cw[4] = {wx0*wy0, wx1*wy0, wx0*wy1, wx1*wy1};
        #pragma unroll
        for (int q = 0; q < 4; q++) {
            if (cx[q] >= 0.0f && cx[q] <= 87.0f && cy[q] >= 0.0f && cy[q] <= 31.0f && lane < 24) {
                const float4* base = (const float4*)(g_imgT +
                    (((size_t)n*H_FEAT + (int)cy[q])*W_FEAT + (int)cx[q]) * C_IMG);
                float4 f = __ldg(base + lane);
                float w = cw[q];
                acc.x += w*f.x; acc.y += w*f.y; acc.z += w*f.z; acc.w += w*f.w;
            }
        }
    }
    if (lane < 24)
        ((float4*)(g_sampled + (size_t)warp*C_IMG))[lane] = acc;
}

// ---------------- sparse conv: one k per block, w[k] in smem ----------------
__global__ void __launch_bounds__(256)
conv_kernel(const float* __restrict__ pts,
            const int*   __restrict__ vc,
            const float* __restrict__ convw) {
    extern __shared__ char smem_raw[];
    float* w_s   = (float*)smem_raw;
    int*   s_out = (int*)(smem_raw + CONV_W_SMEM);
    int*   s_nid = s_out + 512;
    __shared__ int s_np;

    int bid = blockIdx.x;
    int k, slice, nsl;
    if (bid < NB_SELF) { k = 13; slice = bid; nsl = NB_SELF; }
    else {
        int r = bid - NB_SELF;
        int ko = r / NB_OTHER; slice = r % NB_OTHER; nsl = NB_OTHER;
        k = (ko < 13) ? ko : ko + 1;
    }
    int dz = k/9 - 1, dy = (k/3)%3 - 1, dx = k%3 - 1;

    // load conv_w[k] into smem (float4)
    {
        const float4* wk = (const float4*)(convw + (size_t)k*KIN*PTS_DIM);
        float4* ws4 = (float4*)w_s;
        for (int idx = threadIdx.x; idx < (KIN*PTS_DIM)/4; idx += 256) ws4[idx] = wk[idx];
    }

    int start = (int)((long long)slice * M_PTS / nsl);
    int end   = (int)((long long)(slice+1) * M_PTS / nsl);

    int tid = threadIdx.x;
    int sub = tid >> 7;          // 0/1: pair-group subset
    int j   = tid & 127;         // output channel
    const float* wcol = w_s + j;
    const int4* vc4 = (const int4*)vc;

    __syncthreads();

    for (int base = start; base < end; base += 512) {
        int lim = min(512, end - base);
        __syncthreads();
        if (tid == 0) s_np = 0;
        __syncthreads();

        if (k == 13) {
            for (int t = tid; t < lim; t += 256) {
                int i = base + t;
                int4 c4 = vc4[i];
                int cell = (c4.y*GY + c4.z)*GX + c4.w;
                s_out[t] = i;
                s_nid[t] = __ldg(&g_grid[cell]);   // duplicate cells: winner's features
            }
            if (tid == 0) s_np = lim;
        } else {
            for (int t = tid; t < lim; t += 256) {
                int i = base + t;
                int4 c4 = vc4[i];
                int nz = c4.y + dz, ny = c4.z + dy, nx = c4.w + dx;
                if (nz >= 0 && nz < GZ && ny >= 0 && ny < GY && nx >= 0 && nx < GX) {
                    int nid = __ldg(&g_grid[(nz*GY + ny)*GX + nx]);
                    if (nid >= 0) {
                        int pos = atomicAdd(&s_np, 1);
                        s_out[pos] = i; s_nid[pos] = nid;
                    }
                }
            }
        }
        __syncthreads();
        int np = s_np;

        // subsets take alternating groups of 8 pairs
        for (int g0 = sub*8; g0 < np; g0 += 16) {
            const float* rp[8]; const float* rs[8]; int ov[8];
            #pragma unroll
            for (int p = 0; p < 8; p++) {
                int idx = g0 + p;
                int valid = idx < np;
                int nid = valid ? s_nid[idx] : 0;
                ov[p] = valid ? s_out[idx] : -1;
                rp[p] = pts       + (size_t)nid * PTS_DIM;
                rs[p] = g_sampled + (size_t)nid * C_IMG;
            }
            float acc[8];
            #pragma unroll
            for (int p = 0; p < 8; p++) acc[p] = 0.0f;

            // pts part: channels 0..127
            #pragma unroll 4
            for (int c0 = 0; c0 < PTS_DIM; c0 += 4) {
                float w0 = wcol[(c0+0)*PTS_DIM];
                float w1 = wcol[(c0+1)*PTS_DIM];
                float w2 = wcol[(c0+2)*PTS_DIM];
                float w3 = wcol[(c0+3)*PTS_DIM];
                #pragma unroll
                for (int p = 0; p < 8; p++) {
                    float4 f = __ldg((const float4*)(rp[p] + c0));
                    acc[p] = fmaf(f.w, w3, fmaf(f.z, w2, fmaf(f.y, w1, fmaf(f.x, w0, acc[p]))));
                }
            }
            // sampled part: channels 128..223
            #pragma unroll 4
            for (int c0 = 0; c0 < C_IMG; c0 += 4) {
                float w0 = wcol[(PTS_DIM+c0+0)*PTS_DIM];
                float w1 = wcol[(PTS_DIM+c0+1)*PTS_DIM];
                float w2 = wcol[(PTS_DIM+c0+2)*PTS_DIM];
                float w3 = wcol[(PTS_DIM+c0+3)*PTS_DIM];
                #pragma unroll
                for (int p = 0; p < 8; p++) {
                    float4 f = __ldg((const float4*)(rs[p] + c0));
                    acc[p] = fmaf(f.w, w3, fmaf(f.z, w2, fmaf(f.y, w1, fmaf(f.x, w0, acc[p]))));
                }
            }
            #pragma unroll
            for (int p = 0; p < 8; p++)
                if (ov[p] >= 0)
                    atomicAdd(g_acc + (size_t)ov[p]*PTS_DIM + j, acc[p]);
        }
    }
}

// ---------------- BN + ReLU ----------------
__global__ void bn_relu_kernel(float* __restrict__ out) {
    int idx = blockIdx.x * 256 + threadIdx.x;
    if (idx >= M_PTS*PTS_DIM) return;
    int j = idx & 127;
    float y = g_acc[idx] * g_bnscale[j] + g_bnbias[j];
    out[idx] = fmaxf(y, 0.0f);
}

// ---------------- launch ----------------
extern "C" void kernel_launch(void* const* d_in, const int* in_sizes, int n_in,
                              void* d_out, int out_size) {
    const float* pts   = (const float*)d_in[0];
    const int*   vc    = (const int*)  d_in[1];
    const float* img   = (const float*)d_in[2];
    const float* l2i   = (const float*)d_in[3];
    const float* iaug  = (const float*)d_in[4];
    const float* laug  = (const float*)d_in[5];
    const float* convw = (const float*)d_in[6];
    const float* gamma = (const float*)d_in[7];
    const float* beta  = (const float*)d_in[8];
    const float* mean  = (const float*)d_in[9];
    const float* var   = (const float*)d_in[10];
    float* out = (float*)d_out;

    cudaFuncSetAttribute(conv_kernel, cudaFuncAttributeMaxDynamicSharedMemorySize, CONV_SMEM);

    setup_kernel<<<1, 128>>>(l2i, iaug, laug, gamma, beta, mean, var);
    transpose_kernel<<<(N_CAM*H_FEAT*W_FEAT*C_IMG + 255)/256, 256>>>(img);
    init_grid_kernel<<<(GRID_N/4 + 255)/256, 256>>>();
    scatter_kernel<<<(M_PTS + 255)/256, 256>>>(vc);
    zero_acc_kernel<<<((M_PTS*PTS_DIM)/4 + 255)/256, 256>>>();
    sample_kernel<<<M_PTS/8, 256>>>(vc);
    conv_kernel<<<NBLK, 256, CONV_SMEM>>>(pts, vc, convw);
    bn_relu_kernel<<<(M_PTS*PTS_DIM + 255)/256, 256>>>(out);
}

// round 2
// speedup vs baseline: 6.3561x; 6.3561x over previous
#include <cuda_runtime.h>
#include <cuda_bf16.h>

#define M_PTS   200000
#define N_CAM   6
#define C_IMG   96
#define H_FEAT  32
#define W_FEAT  88
#define PTS_DIM 128
#define KIN     224           // 128 + 96
#define GZ      32
#define GY      512
#define GX      448
#define GRID_N  (GZ*GY*GX)    // 7,340,032

#define NTAP_O   26           // non-self taps
#define PAIR_CAP 200000
#define NT_SELF  1563         // ceil(200000/128)
#define NCHUNK   28           // 224/8

// ---------------- device globals (scratch; no cudaMalloc allowed) ----------------
__device__ float g_imgT[N_CAM*H_FEAT*W_FEAT*C_IMG];   // NHWC transposed image feats
__device__ int   g_grid[GRID_N];
__device__ float g_sampled[(size_t)M_PTS*C_IMG];
__device__ float g_acc[(size_t)M_PTS*PTS_DIM];
__device__ int2  g_pairs[(size_t)NTAP_O*PAIR_CAP];    // (out_idx, nid) per tap
__device__ int   g_np[NTAP_O];
__device__ float g_cam[N_CAM*24];
__device__ float g_bnscale[PTS_DIM];
__device__ float g_bnbias[PTS_DIM];

// ---------------- setup: matrix precompute + BN constants + counter reset ----------------
__global__ void setup_kernel(const float* __restrict__ l2i,
                             const float* __restrict__ iaug,
                             const float* __restrict__ laug,
                             const float* __restrict__ gamma,
                             const float* __restrict__ beta,
                             const float* __restrict__ mean,
                             const float* __restrict__ var) {
    int t = threadIdx.x;
    if (t < PTS_DIM) {
        float s = rsqrtf(var[t] + 1e-5f) * gamma[t];
        g_bnscale[t] = s;
        g_bnbias[t]  = beta[t] - mean[t] * s;
    }
    if (t < NTAP_O) g_np[t] = 0;
    if (t == 0) {
        float a0=laug[0],a1=laug[1],a2=laug[2];
        float a3=laug[4],a4=laug[5],a5=laug[6];
        float a6=laug[8],a7=laug[9],a8=laug[10];
        float tx=laug[3], ty=laug[7], tz=laug[11];
        float det = a0*(a4*a8-a5*a7) - a1*(a3*a8-a5*a6) + a2*(a3*a7-a4*a6);
        float id = 1.0f/det;
        float inv[9] = {
            (a4*a8-a5*a7)*id, (a2*a7-a1*a8)*id, (a1*a5-a2*a4)*id,
            (a5*a6-a3*a8)*id, (a0*a8-a2*a6)*id, (a2*a3-a0*a5)*id,
            (a3*a7-a4*a6)*id, (a1*a6-a0*a7)*id, (a0*a4-a1*a3)*id };
        for (int n = 0; n < N_CAM; n++) {
            const float* L = l2i + n*16;
            float P[9], q[3];
            for (int r = 0; r < 3; r++) {
                for (int c = 0; c < 3; c++)
                    P[r*3+c] = L[r*4+0]*inv[0*3+c] + L[r*4+1]*inv[1*3+c] + L[r*4+2]*inv[2*3+c];
                q[r] = L[r*4+3] - (P[r*3+0]*tx + P[r*3+1]*ty + P[r*3+2]*tz);
            }
            float* gc = g_cam + n*24;
            for (int r = 0; r < 3; r++) {
                gc[r*4+0]=P[r*3+0]; gc[r*4+1]=P[r*3+1]; gc[r*4+2]=P[r*3+2]; gc[r*4+3]=q[r];
            }
            const float* A = iaug + n*16;
            for (int r = 0; r < 2; r++) {
                gc[12+r*4+0]=A[r*4+0]; gc[12+r*4+1]=A[r*4+1]; gc[12+r*4+2]=A[r*4+2]; gc[12+r*4+3]=A[r*4+3];
            }
        }
    }
}

// ---------------- transpose img_feats NCHW -> NHWC ----------------
__global__ void transpose_kernel(const float* __restrict__ img) {
    int o = blockIdx.x * 256 + threadIdx.x;
    const int TOT = N_CAM*H_FEAT*W_FEAT*C_IMG;
    if (o >= TOT) return;
    int c = o % C_IMG; int rest = o / C_IMG;
    int x = rest % W_FEAT; rest /= W_FEAT;
    int y = rest % H_FEAT; int n = rest / H_FEAT;
    g_imgT[o] = img[(((size_t)n*C_IMG + c)*H_FEAT + y)*W_FEAT + x];
}

__global__ void init_grid_kernel() {
    int idx = blockIdx.x * 256 + threadIdx.x;
    if (idx < GRID_N/4) ((int4*)g_grid)[idx] = make_int4(-1,-1,-1,-1);
}

__global__ void scatter_kernel(const int* __restrict__ vc) {
    int i = blockIdx.x * 256 + threadIdx.x;
    if (i >= M_PTS) return;
    int4 c4 = ((const int4*)vc)[i];
    int cell = (c4.y*GY + c4.z)*GX + c4.w;
    atomicMax(&g_grid[cell], i);     // last-write-wins (highest index) for duplicates
}

__global__ void zero_acc_kernel() {
    int idx = blockIdx.x * 256 + threadIdx.x;
    if (idx < (M_PTS*PTS_DIM)/4) ((float4*)g_acc)[idx] = make_float4(0.f,0.f,0.f,0.f);
}

// ---------------- projection + bilinear sampling (warp per voxel) ----------------
__global__ void sample_kernel(const int* __restrict__ vc) {
    int warp = (blockIdx.x * blockDim.x + threadIdx.x) >> 5;
    int lane = threadIdx.x & 31;
    if (warp >= M_PTS) return;
    int4 c4 = ((const int4*)vc)[warp];
    float px = (float)c4.w, py = (float)c4.z, pz = (float)c4.y;
    float4 acc = make_float4(0.f,0.f,0.f,0.f);

    #pragma unroll 1
    for (int n = 0; n < N_CAM; n++) {
        const float* cam = g_cam + n*24;
        float X = cam[0]*px + cam[1]*py + cam[2]*pz  + cam[3];
        float Y = cam[4]*px + cam[5]*py + cam[6]*pz  + cam[7];
        float Z = cam[8]*px + cam[9]*py + cam[10]*pz + cam[11];
        float z = fminf(fmaxf(Z, 1e-5f), 100000.0f);
        float rz = 1.0f / z;
        float vx = X*rz, vy = Y*rz;
        float u = cam[12]*vx + cam[13]*vy + cam[14]*z + cam[15];
        float v = cam[16]*vx + cam[17]*vy + cam[18]*z + cam[19];
        float xf = u * (87.0f/704.0f);
        float yf = v * (31.0f/256.0f);
        float x0 = floorf(xf), y0 = floorf(yf);
        float wx1 = xf - x0, wy1 = yf - y0;
        float wx0 = 1.0f - wx1, wy0 = 1.0f - wy1;

        float cx[4] = {x0, x0+1.0f, x0,      x0+1.0f};
        float cy[4] = {y0, y0,      y0+1.0f, y0+1.0f};
        float cw[4] = {wx0*wy0, wx1*wy0, wx0*wy1, wx1*wy1};
        #pragma unroll
        for (int q = 0; q < 4; q++) {
            if (cx[q] >= 0.0f && cx[q] <= 87.0f && cy[q] >= 0.0f && cy[q] <= 31.0f && lane < 24) {
                const float4* base = (const float4*)(g_imgT +
                    (((size_t)n*H_FEAT + (int)cy[q])*W_FEAT + (int)cx[q]) * C_IMG);
                float4 f = __ldg(base + lane);
                float w = cw[q];
                acc.x += w*f.x; acc.y += w*f.y; acc.z += w*f.z; acc.w += w*f.w;
            }
        }
    }
    if (lane < 24)
        ((float4*)(g_sampled + (size_t)warp*C_IMG))[lane] = acc;
}

// ---------------- build per-tap pair lists (warp ballot + block-aggregated counters) --------
__global__ void build_pairs_kernel(const int* __restrict__ vc) {
    int tid = threadIdx.x;
    int i = blockIdx.x * 256 + tid;
    int lane = tid & 31;
    bool live = i < M_PTS;
    int4 c4 = live ? ((const int4*)vc)[i] : make_int4(0,0,0,0);

    __shared__ int s_cnt[NTAP_O];
    __shared__ int s_gbase[NTAP_O];
    if (tid < NTAP_O) s_cnt[tid] = 0;
    __syncthreads();

    int nids[NTAP_O];
    int idxs[NTAP_O];
    unsigned vm = 0;

    #pragma unroll
    for (int t = 0; t < NTAP_O; t++) {
        int k = (t < 13) ? t : t + 1;
        int dz = k/9 - 1, dy = (k/3)%3 - 1, dx = k%3 - 1;
        int nz = c4.y + dz, ny = c4.z + dy, nx = c4.w + dx;
        bool valid = live && nz >= 0 && nz < GZ && ny >= 0 && ny < GY && nx >= 0 && nx < GX;
        int nid = -1;
        if (valid) nid = __ldg(&g_grid[(nz*GY + ny)*GX + nx]);
        valid = valid && (nid >= 0);
        unsigned m = __ballot_sync(0xffffffffu, valid);
        if (m != 0) {
            int ldr = __ffs(m) - 1;
            int wb = 0;
            if (lane == ldr) wb = atomicAdd(&s_cnt[t], __popc(m));
            wb = __shfl_sync(0xffffffffu, wb, ldr);
            if (valid) {
                int rank = __popc(m & ((1u << lane) - 1u));
                nids[t] = nid;
                idxs[t] = wb + rank;
                vm |= (1u << t);
            }
        }
    }
    __syncthreads();
    if (tid < NTAP_O) s_gbase[tid] = atomicAdd(&g_np[tid], s_cnt[tid]);
    __syncthreads();
    #pragma unroll
    for (int t = 0; t < NTAP_O; t++) {
        if ((vm >> t) & 1u)
            g_pairs[(size_t)t*PAIR_CAP + s_gbase[t] + idxs[t]] = make_int2(i, nids[t]);
    }
}

// ---------------- sparse conv as 128x128xK224 register-tiled SGEMM ----------------
// SELF=false: grid (64, 26), persistent over tiles of tap t, atomicAdd into g_acc
// SELF=true : grid (1563), one tile each, k=13, fused g_acc add + BN + ReLU -> out
template<bool SELF>
__global__ void __launch_bounds__(256, 2)
conv_gemm_kernel(const float* __restrict__ pts,
                 const int*   __restrict__ vc,
                 const float* __restrict__ convw,
                 float*       __restrict__ out) {
    __shared__ float s_a[2][8][128];
    __shared__ float s_b[2][8][128];
    __shared__ int s_out[128];
    __shared__ int s_nid[128];

    int tid = threadIdx.x;
    int k, np, tile0, tstep;
    if (SELF) { k = 13; np = M_PTS; tile0 = blockIdx.x; tstep = NT_SELF; }
    else {
        int t = blockIdx.y;
        k = (t < 13) ? t : t + 1;
        np = g_np[t];
        tile0 = blockIdx.x; tstep = 64;
    }
    const float* wk = convw + (size_t)k*KIN*PTS_DIM;
    const int tpair = SELF ? 0 : (int)blockIdx.y;

    int ty = tid >> 4, tx = tid & 15;       // 16x16 thread grid
    int myrow = tid >> 1, half = tid & 1;   // for A gather: 2 threads/row

    for (int tile = tile0; tile*128 < np; tile += tstep) {
        __syncthreads();   // protect s_out/s_nid from previous tile epilogue
        int base = tile*128;
        if (tid < 128) {
            int r = base + tid;
            int o = -1, nid = 0;
            if (r < np) {
                if (SELF) {
                    int4 c4 = ((const int4*)vc)[r];
                    o = r;
                    nid = __ldg(&g_grid[(c4.y*GY + c4.z)*GX + c4.w]);
                } else {
                    int2 pr = g_pairs[(size_t)tpair*PAIR_CAP + r];
                    o = pr.x; nid = pr.y;
                }
            }
            s_out[tid] = o;
            s_nid[tid] = nid;
        }
        __syncthreads();

        int nid = s_nid[myrow];
        const float* arow_p = pts       + (size_t)nid*PTS_DIM + half*4;
        const float* arow_s = g_sampled + (size_t)nid*C_IMG  + half*4;

        float acc[8][8];
        #pragma unroll
        for (int p = 0; p < 8; p++)
            #pragma unroll
            for (int q = 0; q < 8; q++) acc[p][q] = 0.0f;

        // preload chunk 0
        float4 av = *(const float4*)(arow_p);
        float4 bv = *(const float4*)(wk + tid*4);
        {
            s_a[0][half*4+0][myrow] = av.x;
            s_a[0][half*4+1][myrow] = av.y;
            s_a[0][half*4+2][myrow] = av.z;
            s_a[0][half*4+3][myrow] = av.w;
            ((float4*)&s_b[0][0][0])[tid] = bv;
        }
        __syncthreads();

        int buf = 0;
        #pragma unroll 1
        for (int c = 0; c < NCHUNK; c++) {
            if (c + 1 < NCHUNK) {
                int kc0 = (c+1)*8;
                const float* ap = (kc0 < PTS_DIM) ? (arow_p + kc0) : (arow_s + (kc0 - PTS_DIM));
                av = *(const float4*)ap;
                bv = *(const float4*)(wk + kc0*PTS_DIM + tid*4);
            }
            #pragma unroll
            for (int kc = 0; kc < 8; kc++) {
                float4 a0 = *(float4*)&s_a[buf][kc][ty*8];
                float4 a1 = *(float4*)&s_a[buf][kc][ty*8+4];
                float4 b0 = *(float4*)&s_b[buf][kc][tx*8];
                float4 b1 = *(float4*)&s_b[buf][kc][tx*8+4];
                float ar[8] = {a0.x,a0.y,a0.z,a0.w,a1.x,a1.y,a1.z,a1.w};
                float br[8] = {b0.x,b0.y,b0.z,b0.w,b1.x,b1.y,b1.z,b1.w};
                #pragma unroll
                for (int p = 0; p < 8; p++)
                    #pragma unroll
                    for (int q = 0; q < 8; q++)
                        acc[p][q] = fmaf(ar[p], br[q], acc[p][q]);
            }
            if (c + 1 < NCHUNK) {
                int nb = buf ^ 1;
                s_a[nb][half*4+0][myrow] = av.x;
                s_a[nb][half*4+1][myrow] = av.y;
                s_a[nb][half*4+2][myrow] = av.z;
                s_a[nb][half*4+3][myrow] = av.w;
                ((float4*)&s_b[nb][0][0])[tid] = bv;
            }
            __syncthreads();
            buf ^= 1;
        }

        // epilogue
        if (SELF) {
            float sc[8], bi[8];
            #pragma unroll
            for (int q = 0; q < 8; q++) {
                sc[q] = g_bnscale[tx*8+q];
                bi[q] = g_bnbias[tx*8+q];
            }
            #pragma unroll
            for (int p = 0; p < 8; p++) {
                int o = s_out[ty*8+p];
                if (o >= 0) {
                    const float4* gp = (const float4*)(g_acc + (size_t)o*PTS_DIM + tx*8);
                    float4 g0 = gp[0], g1 = gp[1];
                    float4 r0, r1;
                    r0.x = fmaxf((acc[p][0]+g0.x)*sc[0]+bi[0], 0.f);
                    r0.y = fmaxf((acc[p][1]+g0.y)*sc[1]+bi[1], 0.f);
                    r0.z = fmaxf((acc[p][2]+g0.z)*sc[2]+bi[2], 0.f);
                    r0.w = fmaxf((acc[p][3]+g0.w)*sc[3]+bi[3], 0.f);
                    r1.x = fmaxf((acc[p][4]+g1.x)*sc[4]+bi[4], 0.f);
                    r1.y = fmaxf((acc[p][5]+g1.y)*sc[5]+bi[5], 0.f);
                    r1.z = fmaxf((acc[p][6]+g1.z)*sc[6]+bi[6], 0.f);
                    r1.w = fmaxf((acc[p][7]+g1.w)*sc[7]+bi[7], 0.f);
                    float4* op = (float4*)(out + (size_t)o*PTS_DIM + tx*8);
                    op[0] = r0; op[1] = r1;
                }
            }
        } else {
            #pragma unroll
            for (int p = 0; p < 8; p++) {
                int o = s_out[ty*8+p];
                if (o >= 0) {
                    float* gp = g_acc + (size_t)o*PTS_DIM + tx*8;
                    #pragma unroll
                    for (int q = 0; q < 8; q++)
                        atomicAdd(gp + q, acc[p][q]);
                }
            }
        }
    }
}

// ---------------- launch ----------------
extern "C" void kernel_launch(void* const* d_in, const int* in_sizes, int n_in,
                              void* d_out, int out_size) {
    const float* pts   = (const float*)d_in[0];
    const int*   vc    = (const int*)  d_in[1];
    const float* img   = (const float*)d_in[2];
    const float* l2i   = (const float*)d_in[3];
    const float* iaug  = (const float*)d_in[4];
    const float* laug  = (const float*)d_in[5];
    const float* convw = (const float*)d_in[6];
    const float* gamma = (const float*)d_in[7];
    const float* beta  = (const float*)d_in[8];
    const float* mean  = (const float*)d_in[9];
    const float* var   = (const float*)d_in[10];
    float* out = (float*)d_out;

    setup_kernel<<<1, 128>>>(l2i, iaug, laug, gamma, beta, mean, var);
    transpose_kernel<<<(N_CAM*H_FEAT*W_FEAT*C_IMG + 255)/256, 256>>>(img);
    init_grid_kernel<<<(GRID_N/4 + 255)/256, 256>>>();
    scatter_kernel<<<(M_PTS + 255)/256, 256>>>(vc);
    zero_acc_kernel<<<((M_PTS*PTS_DIM)/4 + 255)/256, 256>>>();
    sample_kernel<<<M_PTS/8, 256>>>(vc);
    build_pairs_kernel<<<(M_PTS + 255)/256, 256>>>(vc);
    conv_gemm_kernel<false><<<dim3(64, NTAP_O), 256>>>(pts, vc, convw, out);
    conv_gemm_kernel<true ><<<NT_SELF, 256>>>(pts, vc, convw, out);
}

// round 3
// speedup vs baseline: 6.5893x; 1.0367x over previous
#include <cuda_runtime.h>
#include <cuda_bf16.h>

#define M_PTS   200000
#define N_CAM   6
#define C_IMG   96
#define H_FEAT  32
#define W_FEAT  88
#define PTS_DIM 128
#define KIN     224           // 128 + 96
#define GZ      32
#define GY      512
#define GX      448
#define GRID_N  (GZ*GY*GX)    // 7,340,032

#define NTAP_O   26           // non-self taps
#define PAIR_CAP 200000
#define NT_SELF  1563         // ceil(200000/128)
#define NCHUNK   28           // 224/8

typedef unsigned long long u64;

// packed f32x2 FMA: d = a*b + d  (two independent fp32 lanes, .rn each)
#define FMA2(d,a,b) asm("fma.rn.f32x2 %0, %1, %2, %0;" : "+l"(d) : "l"(a), "l"(b))
#define PACK2(d,x)  asm("mov.b64 %0, {%1, %1};" : "=l"(d) : "f"(x))
#define UNPACK2(lo,hi,v) asm("mov.b64 {%0, %1}, %2;" : "=f"(lo), "=f"(hi) : "l"(v))

// ---------------- device globals (scratch; no cudaMalloc allowed) ----------------
__device__ float g_imgT[N_CAM*H_FEAT*W_FEAT*C_IMG];   // NHWC transposed image feats
__device__ int   g_grid[GRID_N];
__device__ float g_sampled[(size_t)M_PTS*C_IMG];
__device__ float g_acc[(size_t)M_PTS*PTS_DIM];
__device__ int2  g_pairs[(size_t)NTAP_O*PAIR_CAP];    // (out_idx, nid) per tap
__device__ int   g_np[NTAP_O];
__device__ float g_cam[N_CAM*24];
__device__ float g_bnscale[PTS_DIM];
__device__ float g_bnbias[PTS_DIM];

// ---------------- setup: matrix precompute + BN constants + counter reset ----------------
__global__ void setup_kernel(const float* __restrict__ l2i,
                             const float* __restrict__ iaug,
                             const float* __restrict__ laug,
                             const float* __restrict__ gamma,
                             const float* __restrict__ beta,
                             const float* __restrict__ mean,
                             const float* __restrict__ var) {
    int t = threadIdx.x;
    if (t < PTS_DIM) {
        float s = rsqrtf(var[t] + 1e-5f) * gamma[t];
        g_bnscale[t] = s;
        g_bnbias[t]  = beta[t] - mean[t] * s;
    }
    if (t < NTAP_O) g_np[t] = 0;
    if (t == 0) {
        float a0=laug[0],a1=laug[1],a2=laug[2];
        float a3=laug[4],a4=laug[5],a5=laug[6];
        float a6=laug[8],a7=laug[9],a8=laug[10];
        float tx=laug[3], ty=laug[7], tz=laug[11];
        float det = a0*(a4*a8-a5*a7) - a1*(a3*a8-a5*a6) + a2*(a3*a7-a4*a6);
        float id = 1.0f/det;
        float inv[9] = {
            (a4*a8-a5*a7)*id, (a2*a7-a1*a8)*id, (a1*a5-a2*a4)*id,
            (a5*a6-a3*a8)*id, (a0*a8-a2*a6)*id, (a2*a3-a0*a5)*id,
            (a3*a7-a4*a6)*id, (a1*a6-a0*a7)*id, (a0*a4-a1*a3)*id };
        for (int n = 0; n < N_CAM; n++) {
            const float* L = l2i + n*16;
            float P[9], q[3];
            for (int r = 0; r < 3; r++) {
                for (int c = 0; c < 3; c++)
                    P[r*3+c] = L[r*4+0]*inv[0*3+c] + L[r*4+1]*inv[1*3+c] + L[r*4+2]*inv[2*3+c];
                q[r] = L[r*4+3] - (P[r*3+0]*tx + P[r*3+1]*ty + P[r*3+2]*tz);
            }
            float* gc = g_cam + n*24;
            for (int r = 0; r < 3; r++) {
                gc[r*4+0]=P[r*3+0]; gc[r*4+1]=P[r*3+1]; gc[r*4+2]=P[r*3+2]; gc[r*4+3]=q[r];
            }
            const float* A = iaug + n*16;
            for (int r = 0; r < 2; r++) {
                gc[12+r*4+0]=A[r*4+0]; gc[12+r*4+1]=A[r*4+1]; gc[12+r*4+2]=A[r*4+2]; gc[12+r*4+3]=A[r*4+3];
            }
        }
    }
}

// ---------------- transpose img_feats NCHW -> NHWC ----------------
__global__ void transpose_kernel(const float* __restrict__ img) {
    int o = blockIdx.x * 256 + threadIdx.x;
    const int TOT = N_CAM*H_FEAT*W_FEAT*C_IMG;
    if (o >= TOT) return;
    int c = o % C_IMG; int rest = o / C_IMG;
    int x = rest % W_FEAT; rest /= W_FEAT;
    int y = rest % H_FEAT; int n = rest / H_FEAT;
    g_imgT[o] = img[(((size_t)n*C_IMG + c)*H_FEAT + y)*W_FEAT + x];
}

__global__ void init_grid_kernel() {
    int idx = blockIdx.x * 256 + threadIdx.x;
    if (idx < GRID_N/4) ((int4*)g_grid)[idx] = make_int4(-1,-1,-1,-1);
}

__global__ void scatter_kernel(const int* __restrict__ vc) {
    int i = blockIdx.x * 256 + threadIdx.x;
    if (i >= M_PTS) return;
    int4 c4 = ((const int4*)vc)[i];
    int cell = (c4.y*GY + c4.z)*GX + c4.w;
    atomicMax(&g_grid[cell], i);     // last-write-wins (highest index) for duplicates
}

__global__ void zero_acc_kernel() {
    int idx = blockIdx.x * 256 + threadIdx.x;
    if (idx < (M_PTS*PTS_DIM)/4) ((float4*)g_acc)[idx] = make_float4(0.f,0.f,0.f,0.f);
}

// ---------------- projection + bilinear sampling (warp per voxel) ----------------
__global__ void sample_kernel(const int* __restrict__ vc) {
    int warp = (blockIdx.x * blockDim.x + threadIdx.x) >> 5;
    int lane = threadIdx.x & 31;
    if (warp >= M_PTS) return;
    int4 c4 = ((const int4*)vc)[warp];
    float px = (float)c4.w, py = (float)c4.z, pz = (float)c4.y;
    float4 acc = make_float4(0.f,0.f,0.f,0.f);

    #pragma unroll 1
    for (int n = 0; n < N_CAM; n++) {
        const float* cam = g_cam + n*24;
        float X = cam[0]*px + cam[1]*py + cam[2]*pz  + cam[3];
        float Y = cam[4]*px + cam[5]*py + cam[6]*pz  + cam[7];
        float Z = cam[8]*px + cam[9]*py + cam[10]*pz + cam[11];
        float z = fminf(fmaxf(Z, 1e-5f), 100000.0f);
        float rz = 1.0f / z;
        float vx = X*rz, vy = Y*rz;
        float u = cam[12]*vx + cam[13]*vy + cam[14]*z + cam[15];
        float v = cam[16]*vx + cam[17]*vy + cam[18]*z + cam[19];
        float xf = u * (87.0f/704.0f);
        float yf = v * (31.0f/256.0f);
        float x0 = floorf(xf), y0 = floorf(yf);
        float wx1 = xf - x0, wy1 = yf - y0;
        float wx0 = 1.0f - wx1, wy0 = 1.0f - wy1;

        float cx[4] = {x0, x0+1.0f, x0,      x0+1.0f};
        float cy[4] = {y0, y0,      y0+1.0f, y0+1.0f};
        float cw[4] = {wx0*wy0, wx1*wy0, wx0*wy1, wx1*wy1};
        #pragma unroll
        for (int q = 0; q < 4; q++) {
            if (cx[q] >= 0.0f && cx[q] <= 87.0f && cy[q] >= 0.0f && cy[q] <= 31.0f && lane < 24) {
                const float4* base = (const float4*)(g_imgT +
                    (((size_t)n*H_FEAT + (int)cy[q])*W_FEAT + (int)cx[q]) * C_IMG);
                float4 f = __ldg(base + lane);
                float w = cw[q];
                acc.x += w*f.x; acc.y += w*f.y; acc.z += w*f.z; acc.w += w*f.w;
            }
        }
    }
    if (lane < 24)
        ((float4*)(g_sampled + (size_t)warp*C_IMG))[lane] = acc;
}

// ---------------- build per-tap pair lists (warp ballot + block-aggregated counters) --------
__global__ void build_pairs_kernel(const int* __restrict__ vc) {
    int tid = threadIdx.x;
    int i = blockIdx.x * 256 + tid;
    int lane = tid & 31;
    bool live = i < M_PTS;
    int4 c4 = live ? ((const int4*)vc)[i] : make_int4(0,0,0,0);

    __shared__ int s_cnt[NTAP_O];
    __shared__ int s_gbase[NTAP_O];
    if (tid < NTAP_O) s_cnt[tid] = 0;
    __syncthreads();

    int nids[NTAP_O];
    int idxs[NTAP_O];
    unsigned vm = 0;

    #pragma unroll
    for (int t = 0; t < NTAP_O; t++) {
        int k = (t < 13) ? t : t + 1;
        int dz = k/9 - 1, dy = (k/3)%3 - 1, dx = k%3 - 1;
        int nz = c4.y + dz, ny = c4.z + dy, nx = c4.w + dx;
        bool valid = live && nz >= 0 && nz < GZ && ny >= 0 && ny < GY && nx >= 0 && nx < GX;
        int nid = -1;
        if (valid) nid = __ldg(&g_grid[(nz*GY + ny)*GX + nx]);
        valid = valid && (nid >= 0);
        unsigned m = __ballot_sync(0xffffffffu, valid);
        if (m != 0) {
            int ldr = __ffs(m) - 1;
            int wb = 0;
            if (lane == ldr) wb = atomicAdd(&s_cnt[t], __popc(m));
            wb = __shfl_sync(0xffffffffu, wb, ldr);
            if (valid) {
                int rank = __popc(m & ((1u << lane) - 1u));
                nids[t] = nid;
                idxs[t] = wb + rank;
                vm |= (1u << t);
            }
        }
    }
    __syncthreads();
    if (tid < NTAP_O) s_gbase[tid] = atomicAdd(&g_np[tid], s_cnt[tid]);
    __syncthreads();
    #pragma unroll
    for (int t = 0; t < NTAP_O; t++) {
        if ((vm >> t) & 1u)
            g_pairs[(size_t)t*PAIR_CAP + s_gbase[t] + idxs[t]] = make_int2(i, nids[t]);
    }
}

// ---------------- sparse conv as 128x128xK224 register-tiled SGEMM (f32x2 packed) ------
template<bool SELF>
__global__ void __launch_bounds__(256, 2)
conv_gemm_kernel(const float* __restrict__ pts,
                 const int*   __restrict__ vc,
                 const float* __restrict__ convw,
                 float*       __restrict__ out) {
    __shared__ float s_a[2][8][128];
    __shared__ float s_b[2][8][128];
    __shared__ int s_out[128];
    __shared__ int s_nid[128];

    int tid = threadIdx.x;
    int k, np, tile0, tstep;
    if (SELF) { k = 13; np = M_PTS; tile0 = blockIdx.x; tstep = NT_SELF; }
    else {
        int t = blockIdx.y;
        k = (t < 13) ? t : t + 1;
        np = g_np[t];
        tile0 = blockIdx.x; tstep = 64;
    }
    const float* wk = convw + (size_t)k*KIN*PTS_DIM;
    const int tpair = SELF ? 0 : (int)blockIdx.y;

    int ty = tid >> 4, tx = tid & 15;       // 16x16 thread grid
    int myrow = tid >> 1, half = tid & 1;   // for A gather: 2 threads/row

    for (int tile = tile0; tile*128 < np; tile += tstep) {
        __syncthreads();   // protect s_out/s_nid from previous tile epilogue
        int base = tile*128;
        if (tid < 128) {
            int r = base + tid;
            int o = -1, nid = 0;
            if (r < np) {
                if (SELF) {
                    int4 c4 = ((const int4*)vc)[r];
                    o = r;
                    nid = __ldg(&g_grid[(c4.y*GY + c4.z)*GX + c4.w]);
                } else {
                    int2 pr = g_pairs[(size_t)tpair*PAIR_CAP + r];
                    o = pr.x; nid = pr.y;
                }
            }
            s_out[tid] = o;
            s_nid[tid] = nid;
        }
        __syncthreads();

        int nid = s_nid[myrow];
        const float* arow_p = pts       + (size_t)nid*PTS_DIM + half*4;
        const float* arow_s = g_sampled + (size_t)nid*C_IMG  + half*4;

        u64 acc2[8][4];     // [p][q-pair], 2 output channels per entry
        #pragma unroll
        for (int p = 0; p < 8; p++)
            #pragma unroll
            for (int q = 0; q < 4; q++) acc2[p][q] = 0ull;

        // preload chunk 0
        float4 av = *(const float4*)(arow_p);
        float4 bv = *(const float4*)(wk + tid*4);
        {
            s_a[0][half*4+0][myrow] = av.x;
            s_a[0][half*4+1][myrow] = av.y;
            s_a[0][half*4+2][myrow] = av.z;
            s_a[0][half*4+3][myrow] = av.w;
            ((float4*)&s_b[0][0][0])[tid] = bv;
        }
        __syncthreads();

        int buf = 0;
        #pragma unroll 1
        for (int c = 0; c < NCHUNK; c++) {
            if (c + 1 < NCHUNK) {
                int kc0 = (c+1)*8;
                const float* ap = (kc0 < PTS_DIM) ? (arow_p + kc0) : (arow_s + (kc0 - PTS_DIM));
                av = *(const float4*)ap;
                bv = *(const float4*)(wk + kc0*PTS_DIM + tid*4);
            }
            #pragma unroll
            for (int kc = 0; kc < 8; kc++) {
                float4 a0 = *(float4*)&s_a[buf][kc][ty*8];
                float4 a1 = *(float4*)&s_a[buf][kc][ty*8+4];
                ulonglong2 bq0 = *(ulonglong2*)&s_b[buf][kc][tx*8];
                ulonglong2 bq1 = *(ulonglong2*)&s_b[buf][kc][tx*8+4];
                u64 b2[4] = {bq0.x, bq0.y, bq1.x, bq1.y};
                float ar[8] = {a0.x,a0.y,a0.z,a0.w,a1.x,a1.y,a1.z,a1.w};
                #pragma unroll
                for (int p = 0; p < 8; p++) {
                    u64 ad;
                    PACK2(ad, ar[p]);
                    FMA2(acc2[p][0], ad, b2[0]);
                    FMA2(acc2[p][1], ad, b2[1]);
                    FMA2(acc2[p][2], ad, b2[2]);
                    FMA2(acc2[p][3], ad, b2[3]);
                }
            }
            if (c + 1 < NCHUNK) {
                int nb = buf ^ 1;
                s_a[nb][half*4+0][myrow] = av.x;
                s_a[nb][half*4+1][myrow] = av.y;
                s_a[nb][half*4+2][myrow] = av.z;
                s_a[nb][half*4+3][myrow] = av.w;
                ((float4*)&s_b[nb][0][0])[tid] = bv;
            }
            __syncthreads();
            buf ^= 1;
        }

        // unpack accumulators
        float acc[8][8];
        #pragma unroll
        for (int p = 0; p < 8; p++)
            #pragma unroll
            for (int q = 0; q < 4; q++)
                UNPACK2(acc[p][2*q], acc[p][2*q+1], acc2[p][q]);

        // epilogue
        if (SELF) {
            float sc[8], bi[8];
            #pragma unroll
            for (int q = 0; q < 8; q++) {
                sc[q] = g_bnscale[tx*8+q];
                bi[q] = g_bnbias[tx*8+q];
            }
            #pragma unroll
            for (int p = 0; p < 8; p++) {
                int o = s_out[ty*8+p];
                if (o >= 0) {
                    const float4* gp = (const float4*)(g_acc + (size_t)o*PTS_DIM + tx*8);
                    float4 g0 = gp[0], g1 = gp[1];
                    float4 r0, r1;
                    r0.x = fmaxf((acc[p][0]+g0.x)*sc[0]+bi[0], 0.f);
                    r0.y = fmaxf((acc[p][1]+g0.y)*sc[1]+bi[1], 0.f);
                    r0.z = fmaxf((acc[p][2]+g0.z)*sc[2]+bi[2], 0.f);
                    r0.w = fmaxf((acc[p][3]+g0.w)*sc[3]+bi[3], 0.f);
                    r1.x = fmaxf((acc[p][4]+g1.x)*sc[4]+bi[4], 0.f);
                    r1.y = fmaxf((acc[p][5]+g1.y)*sc[5]+bi[5], 0.f);
                    r1.z = fmaxf((acc[p][6]+g1.z)*sc[6]+bi[6], 0.f);
                    r1.w = fmaxf((acc[p][7]+g1.w)*sc[7]+bi[7], 0.f);
                    float4* op = (float4*)(out + (size_t)o*PTS_DIM + tx*8);
                    op[0] = r0; op[1] = r1;
                }
            }
        } else {
            #pragma unroll
            for (int p = 0; p < 8; p++) {
                int o = s_out[ty*8+p];
                if (o >= 0) {
                    float* gp = g_acc + (size_t)o*PTS_DIM + tx*8;
                    #pragma unroll
                    for (int q = 0; q < 8; q++)
                        atomicAdd(gp + q, acc[p][q]);
                }
            }
        }
    }
}

// ---------------- launch ----------------
extern "C" void kernel_launch(void* const* d_in, const int* in_sizes, int n_in,
                              void* d_out, int out_size) {
    const float* pts   = (const float*)d_in[0];
    const int*   vc    = (const int*)  d_in[1];
    const float* img   = (const float*)d_in[2];
    const float* l2i   = (const float*)d_in[3];
    const float* iaug  = (const float*)d_in[4];
    const float* laug  = (const float*)d_in[5];
    const float* convw = (const float*)d_in[6];
    const float* gamma = (const float*)d_in[7];
    const float* beta  = (const float*)d_in[8];
    const float* mean  = (const float*)d_in[9];
    const float* var   = (const float*)d_in[10];
    float* out = (float*)d_out;

    setup_kernel<<<1, 128>>>(l2i, iaug, laug, gamma, beta, mean, var);
    transpose_kernel<<<(N_CAM*H_FEAT*W_FEAT*C_IMG + 255)/256, 256>>>(img);
    init_grid_kernel<<<(GRID_N/4 + 255)/256, 256>>>();
    scatter_kernel<<<(M_PTS + 255)/256, 256>>>(vc);
    zero_acc_kernel<<<((M_PTS*PTS_DIM)/4 + 255)/256, 256>>>();
    sample_kernel<<<M_PTS/8, 256>>>(vc);
    build_pairs_kernel<<<(M_PTS + 255)/256, 256>>>(vc);
    conv_gemm_kernel<false><<<dim3(64, NTAP_O), 256>>>(pts, vc, convw, out);
    conv_gemm_kernel<true ><<<NT_SELF, 256>>>(pts, vc, convw, out);
}